// round 2
// baseline (speedup 1.0000x reference)
#include <cuda_runtime.h>

// KNNInterpolate: out[m, :] = sum_k w[m,k] * s_feats[idx[m,k], :]
// w[m,k] = (1/(d2+eps)) / sum_k (1/(d2+eps))
//
// Inputs (metadata order):
//   d_in[0] s_feats          float32 [65536, 128]
//   d_in[1] q_points         float32 [262144, 3]
//   d_in[2] s_points         float32 [65536, 3]
//   d_in[3] neighbor_indices int32   [262144, 3]   (JAX downcasts int64->int32)
// Output: float32 [262144, 128]

#define C_FEAT 128
#define EPS 1e-8f

__global__ __launch_bounds__(256) void knn_interp_kernel(
    const float* __restrict__ s_feats,
    const float* __restrict__ q_points,
    const float* __restrict__ s_points,
    const int* __restrict__ nidx,
    float4* __restrict__ out,
    int M)
{
    const int warp = (int)((blockIdx.x * blockDim.x + threadIdx.x) >> 5);
    const int lane = threadIdx.x & 31;
    if (warp >= M) return;

    // --- weights (redundant per-lane; all same-address broadcast loads) ---
    const float qx = __ldg(q_points + 3ll * warp + 0);
    const float qy = __ldg(q_points + 3ll * warp + 1);
    const float qz = __ldg(q_points + 3ll * warp + 2);

    const int i0 = __ldg(nidx + 3ll * warp + 0);
    const int i1 = __ldg(nidx + 3ll * warp + 1);
    const int i2 = __ldg(nidx + 3ll * warp + 2);

    float w0, w1, w2;
    {
        float dx = qx - __ldg(s_points + 3ll * i0 + 0);
        float dy = qy - __ldg(s_points + 3ll * i0 + 1);
        float dz = qz - __ldg(s_points + 3ll * i0 + 2);
        w0 = 1.0f / (dx * dx + dy * dy + dz * dz + EPS);
        dx = qx - __ldg(s_points + 3ll * i1 + 0);
        dy = qy - __ldg(s_points + 3ll * i1 + 1);
        dz = qz - __ldg(s_points + 3ll * i1 + 2);
        w1 = 1.0f / (dx * dx + dy * dy + dz * dz + EPS);
        dx = qx - __ldg(s_points + 3ll * i2 + 0);
        dy = qy - __ldg(s_points + 3ll * i2 + 1);
        dz = qz - __ldg(s_points + 3ll * i2 + 2);
        w2 = 1.0f / (dx * dx + dy * dy + dz * dz + EPS);
    }
    const float inv_sum = 1.0f / (w0 + w1 + w2);
    w0 *= inv_sum;
    w1 *= inv_sum;
    w2 *= inv_sum;

    // --- gather + weighted sum: one float4 per lane (coalesced 512B rows) ---
    const float4* __restrict__ f0 =
        (const float4*)(s_feats + (long long)i0 * C_FEAT);
    const float4* __restrict__ f1 =
        (const float4*)(s_feats + (long long)i1 * C_FEAT);
    const float4* __restrict__ f2 =
        (const float4*)(s_feats + (long long)i2 * C_FEAT);

    const float4 a = __ldg(f0 + lane);
    const float4 b = __ldg(f1 + lane);
    const float4 c = __ldg(f2 + lane);

    float4 r;
    r.x = w0 * a.x + w1 * b.x + w2 * c.x;
    r.y = w0 * a.y + w1 * b.y + w2 * c.y;
    r.z = w0 * a.z + w1 * b.z + w2 * c.z;
    r.w = w0 * a.w + w1 * b.w + w2 * c.w;

    out[(long long)warp * (C_FEAT / 4) + lane] = r;
}

extern "C" void kernel_launch(void* const* d_in, const int* in_sizes, int n_in,
                              void* d_out, int out_size)
{
    const float* s_feats = (const float*)d_in[0];
    const float* q_points = (const float*)d_in[1];
    const float* s_points = (const float*)d_in[2];
    const int* nidx = (const int*)d_in[3];
    float4* out = (float4*)d_out;

    const int M = in_sizes[1] / 3;  // q_points has M*3 elements

    const int warps_per_block = 8;          // 256 threads
    const int blocks = (M + warps_per_block - 1) / warps_per_block;
    knn_interp_kernel<<<blocks, warps_per_block * 32>>>(
        s_feats, q_points, s_points, nidx, out, M);
}